// round 6
// baseline (speedup 1.0000x reference)
#include <cuda_runtime.h>
#include <cuda_bf16.h>
#include <cstdint>
#include <cstddef>

#define N_NODES 100000
#define E_EDGES 1000000
#define D_DIM   64
#define NORM_INV 0.01f
#define LN_EPS  1e-5f

// Composite stacked weights: rows 0-63 Wlin, 64-127 Wu=A@Wlin, 128-191 Wv=B@Wlin
__device__ float g_Ws[192 * 64];
__device__ float g_bs[192];           // {blin, A@blin, B@blin}
// Per-node features for the edge kernel (bf16; att path is /100-damped)
__device__ __nv_bfloat16 g_uv[(size_t)N_NODES * 128];  // [node][0:64]=u, [64:128]=v
__device__ __nv_bfloat16 g_xc[(size_t)N_NODES * 64];   // x copy for scatter values
__device__ __nv_bfloat16 g_agg[(size_t)N_NODES * 64];  // bf16 atomic accumulator

__device__ __forceinline__ float fsig(float v) {
    return __fdividef(1.0f, 1.0f + __expf(-v));
}

__device__ __forceinline__ float4 bf16x4_to_f4(uint2 r) {
    const float2 a = __bfloat1622float2(*reinterpret_cast<__nv_bfloat162*>(&r.x));
    const float2 b = __bfloat1622float2(*reinterpret_cast<__nv_bfloat162*>(&r.y));
    return make_float4(a.x, a.y, b.x, b.y);
}

__device__ __forceinline__ unsigned pack_bf2(float a, float b) {
    const __nv_bfloat162 t = __float22bfloat162_rn(make_float2(a, b));
    return *reinterpret_cast<const unsigned*>(&t);
}

// ---------------------------------------------------------------------------
// Kernel 0 (compose): Wu = A@Wlin, Wv = B@Wlin, bu = A@blin, bv = B@blin.
// ---------------------------------------------------------------------------
__global__ void compose_kernel(const float* __restrict__ Wlin,
                               const float* __restrict__ blin,
                               const float* __restrict__ W1)
{
    __shared__ float sWlin[4096], sA[4096], sB[4096];
    const int tid = threadIdx.x;
    for (int i = tid; i < 4096; i += 256) {
        sWlin[i] = Wlin[i];
        const int r = i >> 6, c = i & 63;
        sA[i] = W1[r * 129 + c];
        sB[i] = W1[r * 129 + 64 + c];
    }
    __syncthreads();

    if (blockIdx.x == 0) {
        for (int i = tid; i < 4096; i += 256) g_Ws[i] = sWlin[i];
        if (tid < 64) {
            g_bs[tid] = blin[tid];
            float su = 0.f, sv = 0.f;
            for (int m = 0; m < 64; m++) {
                const float bm = __ldg(blin + m);
                su = fmaf(sA[tid * 64 + m], bm, su);
                sv = fmaf(sB[tid * 64 + m], bm, sv);
            }
            g_bs[64 + tid]  = su;
            g_bs[128 + tid] = sv;
        }
    }

    for (int idx = blockIdx.x * 256 + tid; idx < 4096; idx += gridDim.x * 256) {
        const int j = idx >> 6, k = idx & 63;
        float su = 0.f, sv = 0.f;
        #pragma unroll 8
        for (int m = 0; m < 64; m++) {
            const float w = sWlin[m * 64 + k];
            su = fmaf(sA[j * 64 + m], w, su);
            sv = fmaf(sB[j * 64 + m], w, sv);
        }
        g_Ws[4096 + idx] = su;
        g_Ws[8192 + idx] = sv;
    }
}

// ---------------------------------------------------------------------------
// Kernel 1 (prep): one stacked GEMM per node: {x,u,v} = Ws @ h + bs.
// 8 nodes per warp-iteration; lane owns 6 outputs j = lane + 32g.
// Writes: d_out = x (fp32 residual), g_xc/g_uv bf16, and zeroes g_agg.
// ---------------------------------------------------------------------------
#define PREP_SMEM ((192 * 68 + 192) * 4 + 8 * 8 * 64 * 4)   // 69,376 B

__global__ void __launch_bounds__(256, 2)
prep_kernel(const float* __restrict__ h,
            float* __restrict__ out_res)
{
    extern __shared__ float smem[];
    float*  sWs = smem;                    // 192*68
    float*  sbs = sWs + 192 * 68;          // 192
    float4* sH  = (float4*)(sbs + 192);    // [8 warps][8 nodes][16 f4]

    const int tid = threadIdx.x;
    for (int i = tid; i < 192 * 64; i += 256)
        sWs[(i >> 6) * 68 + (i & 63)] = g_Ws[i];
    if (tid < 192) sbs[tid] = g_bs[tid];
    __syncthreads();

    const int lane = tid & 31;
    const int w    = tid >> 5;
    const int warpGlobal = blockIdx.x * 8 + w;
    const int nWarps     = gridDim.x * 8;

    const float4* wp[6];
    float bj[6];
    #pragma unroll
    for (int g = 0; g < 6; g++) {
        wp[g] = ((const float4*)sWs) + (g * 32 + lane) * 17;
        bj[g] = sbs[g * 32 + lane];
    }
    const float4* hf4 = (const float4*)h;
    float4* sHw = sH + w * (8 * 16);
    unsigned* aggu = (unsigned*)g_agg;

    for (int nb = warpGlobal * 8; nb < N_NODES; nb += nWarps * 8) {
        #pragma unroll
        for (int ep = 0; ep < 8; ep += 2) {
            const int e  = ep + (lane >> 4);
            const int li = lane & 15;
            sHw[e * 16 + li] = hf4[(size_t)(nb + e) * 16 + li];
        }
        __syncwarp();

        float acc[6][8];
        #pragma unroll
        for (int g = 0; g < 6; g++)
            #pragma unroll
            for (int e = 0; e < 8; e++) acc[g][e] = bj[g];

        #pragma unroll 2
        for (int kk = 0; kk < 16; kk++) {
            float4 wr[6];
            #pragma unroll
            for (int g = 0; g < 6; g++) wr[g] = wp[g][kk];
            #pragma unroll
            for (int e = 0; e < 8; e++) {
                const float4 xv = sHw[e * 16 + kk];   // warp-uniform broadcast
                #pragma unroll
                for (int g = 0; g < 6; g++) {
                    acc[g][e] = fmaf(wr[g].x, xv.x, acc[g][e]);
                    acc[g][e] = fmaf(wr[g].y, xv.y, acc[g][e]);
                    acc[g][e] = fmaf(wr[g].z, xv.z, acc[g][e]);
                    acc[g][e] = fmaf(wr[g].w, xv.w, acc[g][e]);
                }
            }
        }

        #pragma unroll
        for (int e = 0; e < 8; e++) {
            const size_t n64  = (size_t)(nb + e) * 64;
            const size_t n128 = (size_t)(nb + e) * 128;
            out_res[n64 + lane]      = acc[0][e];
            out_res[n64 + lane + 32] = acc[1][e];
            g_xc[n64 + lane]       = __float2bfloat16(acc[0][e]);
            g_xc[n64 + lane + 32]  = __float2bfloat16(acc[1][e]);
            g_uv[n128 + lane]      = __float2bfloat16(acc[2][e]);
            g_uv[n128 + lane + 32] = __float2bfloat16(acc[3][e]);
            g_uv[n128 + 64 + lane]      = __float2bfloat16(acc[4][e]);
            g_uv[n128 + 64 + lane + 32] = __float2bfloat16(acc[5][e]);
            aggu[(size_t)(nb + e) * 32 + lane] = 0u;   // zero bf16 accumulator
        }
        __syncwarp();
    }
}

// ---------------------------------------------------------------------------
// Kernel 2 (edge): t = u[row]+v[col]+wd*d+b1; att = sig(W2.silu(t)+b2);
// scatter att*x_col into g_agg[row] with red.global.add.noftz.v4.bf16x2
// (8 lanes x 16B cover all 64 dims). u,v gathers bf16 by 16 lanes.
// ---------------------------------------------------------------------------
__global__ void edge_kernel(const float* __restrict__ dist,
                            const int* __restrict__ edges,  // int32 [2][E]
                            const float* __restrict__ emask,
                            const float* __restrict__ W1,   // [64][129]
                            const float* __restrict__ b1,
                            const float* __restrict__ W2,   // [64]
                            const float* __restrict__ b2p)
{
    const int lane = threadIdx.x & 31;
    const int w    = threadIdx.x >> 5;
    const int hw   = lane >> 4;      // which edge of the pair
    const int li   = lane & 15;      // dim group within edge

    const float4 w2_4 = ((const float4*)W2)[li];
    const float4 b1_4 = ((const float4*)b1)[li];
    float4 wd_4;
    wd_4.x = __ldg(W1 + (size_t)(li * 4 + 0) * 129 + 128);
    wd_4.y = __ldg(W1 + (size_t)(li * 4 + 1) * 129 + 128);
    wd_4.z = __ldg(W1 + (size_t)(li * 4 + 2) * 129 + 128);
    wd_4.w = __ldg(W1 + (size_t)(li * 4 + 3) * 129 + 128);
    const float b2 = b2p[0];

    const uint2* uvp = (const uint2*)g_uv;   // 32 uint2 per node (u:0-15, v:16-31)
    const uint4* xcq = (const uint4*)g_xc;   // 8 uint4 per node

    const int warpGlobal = blockIdx.x * 8 + w;
    const int nWarps     = gridDim.x * 8;

    for (int eb = warpGlobal * 4; eb < E_EDGES; eb += nWarps * 4) {
        #pragma unroll
        for (int s = 0; s < 2; s++) {
            const int e   = eb + s * 2 + hw;            // E%4==0 -> in range
            const int row = __ldg(edges + e);
            const int col = __ldg(edges + E_EDGES + e);
            const float d  = __ldg(dist + e);
            const float em = __ldg(emask + e);

            const float4 u4 = bf16x4_to_f4(__ldg(uvp + (size_t)row * 32 + li));
            const float4 v4 = bf16x4_to_f4(__ldg(uvp + (size_t)col * 32 + 16 + li));

            float4 t;
            t.x = fmaf(d, wd_4.x, u4.x + v4.x + b1_4.x);
            t.y = fmaf(d, wd_4.y, u4.y + v4.y + b1_4.y);
            t.z = fmaf(d, wd_4.z, u4.z + v4.z + b1_4.z);
            t.w = fmaf(d, wd_4.w, u4.w + v4.w + b1_4.w);

            const float h0 = t.x * fsig(t.x);
            const float h1 = t.y * fsig(t.y);
            const float h2 = t.z * fsig(t.z);
            const float h3 = t.w * fsig(t.w);

            float p = fmaf(h0, w2_4.x,
                      fmaf(h1, w2_4.y,
                      fmaf(h2, w2_4.z, h3 * w2_4.w)));
            #pragma unroll
            for (int off = 8; off; off >>= 1)          // reduce within 16 lanes
                p += __shfl_xor_sync(0xffffffffu, p, off);

            const float att = fsig(p + b2) * em * NORM_INV;

            // 8 lanes scatter all 64 dims as bf16x2 quads
            if (li < 8) {
                const uint4 xq = __ldg(xcq + (size_t)col * 8 + li);
                const float4 xa = bf16x4_to_f4(make_uint2(xq.x, xq.y));
                const float4 xb = bf16x4_to_f4(make_uint2(xq.z, xq.w));
                const unsigned p0 = pack_bf2(xa.x * att, xa.y * att);
                const unsigned p1 = pack_bf2(xa.z * att, xa.w * att);
                const unsigned p2 = pack_bf2(xb.x * att, xb.y * att);
                const unsigned p3 = pack_bf2(xb.z * att, xb.w * att);
                __nv_bfloat16* dst = g_agg + (size_t)row * 64 + li * 8;
                asm volatile(
                    "red.global.add.noftz.v4.bf16x2 [%0], {%1, %2, %3, %4};"
                    :: "l"(dst), "r"(p0), "r"(p1), "r"(p2), "r"(p3) : "memory");
            }
        }
    }
}

// ---------------------------------------------------------------------------
// Kernel 3: out = silu(LN(x + agg)).  16 lanes per row (float4 per lane),
// 2 rows per warp. io holds x (fp32); agg is bf16.
// ---------------------------------------------------------------------------
__global__ void ln_kernel(const float* __restrict__ g,
                          const float* __restrict__ bln,
                          float* __restrict__ io)
{
    const int lane = threadIdx.x & 31;
    const int w    = threadIdx.x >> 5;
    const int li   = lane & 15;
    const int row  = blockIdx.x * 16 + w * 2 + (lane >> 4);
    if (row >= N_NODES) return;

    float4 v = ((const float4*)io)[(size_t)row * 16 + li];
    const float4 a = bf16x4_to_f4(__ldg((const uint2*)g_agg + (size_t)row * 16 + li));
    v.x += a.x; v.y += a.y; v.z += a.z; v.w += a.w;

    float s = v.x + v.y + v.z + v.w;
    #pragma unroll
    for (int off = 8; off; off >>= 1)
        s += __shfl_xor_sync(0xffffffffu, s, off);
    const float mu = s * (1.0f / 64.0f);

    const float dx = v.x - mu, dy = v.y - mu, dz = v.z - mu, dw = v.w - mu;
    float q = dx * dx + dy * dy + dz * dz + dw * dw;
    #pragma unroll
    for (int off = 8; off; off >>= 1)
        q += __shfl_xor_sync(0xffffffffu, q, off);
    const float rs = rsqrtf(q * (1.0f / 64.0f) + LN_EPS);

    const float4 gg = __ldg((const float4*)g + li);
    const float4 bb = __ldg((const float4*)bln + li);
    float4 o;
    o.x = fmaf(dx * rs, gg.x, bb.x);
    o.y = fmaf(dy * rs, gg.y, bb.y);
    o.z = fmaf(dz * rs, gg.z, bb.z);
    o.w = fmaf(dw * rs, gg.w, bb.w);
    o.x *= fsig(o.x);
    o.y *= fsig(o.y);
    o.z *= fsig(o.z);
    o.w *= fsig(o.w);
    ((float4*)io)[(size_t)row * 16 + li] = o;
}

// ---------------------------------------------------------------------------
// Launch: compose -> prep -> edge -> layernorm.
// ---------------------------------------------------------------------------
extern "C" void kernel_launch(void* const* d_in, const int* in_sizes, int n_in,
                              void* d_out, int out_size)
{
    const float* h     = (const float*)d_in[0];
    const float* dist  = (const float*)d_in[1];
    const int*   edges = (const int*)d_in[2];   // JAX x64-disabled => int32
    /* d_in[3] node_mask: unused by the reference */
    const float* emask = (const float*)d_in[4];
    const float* Wlin  = (const float*)d_in[5];
    const float* blin  = (const float*)d_in[6];
    const float* W1    = (const float*)d_in[7];
    const float* b1    = (const float*)d_in[8];
    const float* W2    = (const float*)d_in[9];
    const float* b2    = (const float*)d_in[10];
    const float* lng   = (const float*)d_in[11];
    const float* lnb   = (const float*)d_in[12];
    float* out = (float*)d_out;

    cudaFuncSetAttribute(prep_kernel,
                         cudaFuncAttributeMaxDynamicSharedMemorySize, PREP_SMEM);

    compose_kernel<<<16, 256>>>(Wlin, blin, W1);
    prep_kernel<<<592, 256, PREP_SMEM>>>(h, out);
    edge_kernel<<<1184, 256>>>(dist, edges, emask, W1, b1, W2, b2);
    ln_kernel<<<(N_NODES + 15) / 16, 256>>>(lng, lnb, out);
}

// round 7
// speedup vs baseline: 1.3047x; 1.3047x over previous
#include <cuda_runtime.h>
#include <cuda_bf16.h>
#include <cstdint>
#include <cstddef>

#define N_NODES 100000
#define E_EDGES 1000000
#define D_DIM   64
#define NORM_INV 0.01f
#define LN_EPS  1e-5f

// Composite stacked weights: rows 0-63 Wlin, 64-127 Wu=A@Wlin, 128-191 Wv=B@Wlin
__device__ float g_Ws[192 * 64];
__device__ float g_bs[192];           // {blin, A@blin, B@blin}
// Per-node features for the edge kernel (bf16; att path is /100-damped)
__device__ __nv_bfloat16 g_uv[(size_t)N_NODES * 128];  // [node][0:64]=u, [64:128]=v
__device__ __nv_bfloat16 g_xc[(size_t)N_NODES * 64];   // x copy for scatter values
// Packed per-edge metadata {row, col, dist, emask} (16 B)
__device__ int4 g_ep[(size_t)E_EDGES];

__device__ __forceinline__ float fsig(float v) {
    return __fdividef(1.0f, 1.0f + __expf(-v));
}

__device__ __forceinline__ void red_add_v4(float* dst, float a, float b,
                                           float c, float d) {
    asm volatile("red.global.add.v4.f32 [%0], {%1, %2, %3, %4};"
                 :: "l"(dst), "f"(a), "f"(b), "f"(c), "f"(d) : "memory");
}

__device__ __forceinline__ float4 bf16x4_to_f4(uint2 r) {
    const float2 a = __bfloat1622float2(*reinterpret_cast<__nv_bfloat162*>(&r.x));
    const float2 b = __bfloat1622float2(*reinterpret_cast<__nv_bfloat162*>(&r.y));
    return make_float4(a.x, a.y, b.x, b.y);
}

// ---------------------------------------------------------------------------
// Kernel P (pack): g_ep[e] = {row, col, dist, emask}; one LDG.128 per edge
// in the hot loop instead of 4 scalar loads.
// ---------------------------------------------------------------------------
__global__ void pack_kernel(const int* __restrict__ edges,
                            const float* __restrict__ dist,
                            const float* __restrict__ emask)
{
    const int e = blockIdx.x * blockDim.x + threadIdx.x;
    if (e >= E_EDGES) return;
    int4 m;
    m.x = edges[e];
    m.y = edges[E_EDGES + e];
    m.z = __float_as_int(dist[e]);
    m.w = __float_as_int(emask[e]);
    g_ep[e] = m;
}

// ---------------------------------------------------------------------------
// Kernel 0 (compose): Wu = A@Wlin, Wv = B@Wlin, bu = A@blin, bv = B@blin.
// ---------------------------------------------------------------------------
__global__ void compose_kernel(const float* __restrict__ Wlin,
                               const float* __restrict__ blin,
                               const float* __restrict__ W1)
{
    __shared__ float sWlin[4096], sA[4096], sB[4096];
    const int tid = threadIdx.x;
    for (int i = tid; i < 4096; i += 256) {
        sWlin[i] = Wlin[i];
        const int r = i >> 6, c = i & 63;
        sA[i] = W1[r * 129 + c];
        sB[i] = W1[r * 129 + 64 + c];
    }
    __syncthreads();

    if (blockIdx.x == 0) {
        for (int i = tid; i < 4096; i += 256) g_Ws[i] = sWlin[i];
        if (tid < 64) {
            g_bs[tid] = blin[tid];
            float su = 0.f, sv = 0.f;
            for (int m = 0; m < 64; m++) {
                const float bm = __ldg(blin + m);
                su = fmaf(sA[tid * 64 + m], bm, su);
                sv = fmaf(sB[tid * 64 + m], bm, sv);
            }
            g_bs[64 + tid]  = su;
            g_bs[128 + tid] = sv;
        }
    }

    for (int idx = blockIdx.x * 256 + tid; idx < 4096; idx += gridDim.x * 256) {
        const int j = idx >> 6, k = idx & 63;
        float su = 0.f, sv = 0.f;
        #pragma unroll 8
        for (int m = 0; m < 64; m++) {
            const float w = sWlin[m * 64 + k];
            su = fmaf(sA[j * 64 + m], w, su);
            sv = fmaf(sB[j * 64 + m], w, sv);
        }
        g_Ws[4096 + idx] = su;
        g_Ws[8192 + idx] = sv;
    }
}

// ---------------------------------------------------------------------------
// Kernel 1 (prep): one stacked GEMM per node: {x,u,v} = Ws @ h + bs.
// 8 nodes per warp-iteration; lane owns 6 outputs j = lane + 32g.
// Writes: d_out = x (fp32 residual), g_xc = bf16(x), g_uv = bf16(u)||bf16(v).
// ---------------------------------------------------------------------------
#define PREP_SMEM ((192 * 68 + 192) * 4 + 8 * 8 * 64 * 4)   // 69,376 B

__global__ void __launch_bounds__(256, 2)
prep_kernel(const float* __restrict__ h,
            float* __restrict__ out_res)
{
    extern __shared__ float smem[];
    float*  sWs = smem;                    // 192*68
    float*  sbs = sWs + 192 * 68;          // 192
    float4* sH  = (float4*)(sbs + 192);    // [8 warps][8 nodes][16 f4]

    const int tid = threadIdx.x;
    for (int i = tid; i < 192 * 64; i += 256)
        sWs[(i >> 6) * 68 + (i & 63)] = g_Ws[i];
    if (tid < 192) sbs[tid] = g_bs[tid];
    __syncthreads();

    const int lane = tid & 31;
    const int w    = tid >> 5;
    const int warpGlobal = blockIdx.x * 8 + w;
    const int nWarps     = gridDim.x * 8;

    const float4* wp[6];
    float bj[6];
    #pragma unroll
    for (int g = 0; g < 6; g++) {
        wp[g] = ((const float4*)sWs) + (g * 32 + lane) * 17;
        bj[g] = sbs[g * 32 + lane];
    }
    const float4* hf4 = (const float4*)h;
    float4* sHw = sH + w * (8 * 16);

    for (int nb = warpGlobal * 8; nb < N_NODES; nb += nWarps * 8) {
        #pragma unroll
        for (int ep = 0; ep < 8; ep += 2) {
            const int e  = ep + (lane >> 4);
            const int li = lane & 15;
            sHw[e * 16 + li] = hf4[(size_t)(nb + e) * 16 + li];
        }
        __syncwarp();

        float acc[6][8];
        #pragma unroll
        for (int g = 0; g < 6; g++)
            #pragma unroll
            for (int e = 0; e < 8; e++) acc[g][e] = bj[g];

        #pragma unroll 2
        for (int kk = 0; kk < 16; kk++) {
            float4 wr[6];
            #pragma unroll
            for (int g = 0; g < 6; g++) wr[g] = wp[g][kk];
            #pragma unroll
            for (int e = 0; e < 8; e++) {
                const float4 xv = sHw[e * 16 + kk];   // warp-uniform broadcast
                #pragma unroll
                for (int g = 0; g < 6; g++) {
                    acc[g][e] = fmaf(wr[g].x, xv.x, acc[g][e]);
                    acc[g][e] = fmaf(wr[g].y, xv.y, acc[g][e]);
                    acc[g][e] = fmaf(wr[g].z, xv.z, acc[g][e]);
                    acc[g][e] = fmaf(wr[g].w, xv.w, acc[g][e]);
                }
            }
        }

        #pragma unroll
        for (int e = 0; e < 8; e++) {
            const size_t n64  = (size_t)(nb + e) * 64;
            const size_t n128 = (size_t)(nb + e) * 128;
            out_res[n64 + lane]      = acc[0][e];
            out_res[n64 + lane + 32] = acc[1][e];
            g_xc[n64 + lane]       = __float2bfloat16(acc[0][e]);
            g_xc[n64 + lane + 32]  = __float2bfloat16(acc[1][e]);
            g_uv[n128 + lane]      = __float2bfloat16(acc[2][e]);
            g_uv[n128 + lane + 32] = __float2bfloat16(acc[3][e]);
            g_uv[n128 + 64 + lane]      = __float2bfloat16(acc[4][e]);
            g_uv[n128 + 64 + lane + 32] = __float2bfloat16(acc[5][e]);
        }
        __syncwarp();
    }
}

// ---------------------------------------------------------------------------
// Kernel 2 (edge): t = u[row]+v[col]+wd*d+b1; att = sig(W2.silu(t)+b2);
// fp32 red.global.add.v4 of att*x_col into d_out[row].
// Half-warp per edge (lane li owns dims 4li..4li+3), 4 edges per warp-iter.
// Metadata via one LDG.128 per edge; u,v,x gathers bf16.
// ---------------------------------------------------------------------------
__global__ void edge_kernel(const float* __restrict__ W1,   // [64][129]
                            const float* __restrict__ b1,
                            const float* __restrict__ W2,   // [64]
                            const float* __restrict__ b2p,
                            float* __restrict__ agg)        // d_out
{
    const int lane = threadIdx.x & 31;
    const int w    = threadIdx.x >> 5;
    const int hw   = lane >> 4;      // which edge of the pair
    const int li   = lane & 15;      // dim group within edge

    const float4 w2_4 = ((const float4*)W2)[li];
    const float4 b1_4 = ((const float4*)b1)[li];
    float4 wd_4;
    wd_4.x = __ldg(W1 + (size_t)(li * 4 + 0) * 129 + 128);
    wd_4.y = __ldg(W1 + (size_t)(li * 4 + 1) * 129 + 128);
    wd_4.z = __ldg(W1 + (size_t)(li * 4 + 2) * 129 + 128);
    wd_4.w = __ldg(W1 + (size_t)(li * 4 + 3) * 129 + 128);
    const float b2 = b2p[0];

    const uint2* uvp = (const uint2*)g_uv;   // 32 uint2 per node (u:0-15, v:16-31)
    const uint2* xcp = (const uint2*)g_xc;   // 16 uint2 per node

    const int warpGlobal = blockIdx.x * 8 + w;
    const int nWarps     = gridDim.x * 8;

    for (int eb = warpGlobal * 4; eb < E_EDGES; eb += nWarps * 4) {
        #pragma unroll
        for (int s = 0; s < 2; s++) {
            const int e = eb + s * 2 + hw;              // E%4==0 -> in range
            const int4 m = __ldg(g_ep + e);             // {row, col, d, em}
            const int row = m.x;
            const int col = m.y;
            const float d  = __int_as_float(m.z);
            const float em = __int_as_float(m.w);

            const float4 u4 = bf16x4_to_f4(__ldg(uvp + (size_t)row * 32 + li));
            const float4 v4 = bf16x4_to_f4(__ldg(uvp + (size_t)col * 32 + 16 + li));
            const float4 x4 = bf16x4_to_f4(__ldg(xcp + (size_t)col * 16 + li));

            float4 t;
            t.x = fmaf(d, wd_4.x, u4.x + v4.x + b1_4.x);
            t.y = fmaf(d, wd_4.y, u4.y + v4.y + b1_4.y);
            t.z = fmaf(d, wd_4.z, u4.z + v4.z + b1_4.z);
            t.w = fmaf(d, wd_4.w, u4.w + v4.w + b1_4.w);

            const float h0 = t.x * fsig(t.x);
            const float h1 = t.y * fsig(t.y);
            const float h2 = t.z * fsig(t.z);
            const float h3 = t.w * fsig(t.w);

            float p = fmaf(h0, w2_4.x,
                      fmaf(h1, w2_4.y,
                      fmaf(h2, w2_4.z, h3 * w2_4.w)));
            #pragma unroll
            for (int off = 8; off; off >>= 1)          // reduce within 16 lanes
                p += __shfl_xor_sync(0xffffffffu, p, off);

            const float att = fsig(p + b2) * em * NORM_INV;

            float* dst = agg + (size_t)row * 64 + li * 4;
            red_add_v4(dst, x4.x * att, x4.y * att, x4.z * att, x4.w * att);
        }
    }
}

// ---------------------------------------------------------------------------
// Kernel 3: out = silu(LN(io)).  io holds x + agg (fp32).
// 16 lanes per row (float4 per lane), 2 rows per warp.
// ---------------------------------------------------------------------------
__global__ void ln_kernel(const float* __restrict__ g,
                          const float* __restrict__ bln,
                          float* __restrict__ io)
{
    const int lane = threadIdx.x & 31;
    const int w    = threadIdx.x >> 5;
    const int li   = lane & 15;
    const int row  = blockIdx.x * 16 + w * 2 + (lane >> 4);
    if (row >= N_NODES) return;

    float4 v = ((const float4*)io)[(size_t)row * 16 + li];

    float s = v.x + v.y + v.z + v.w;
    #pragma unroll
    for (int off = 8; off; off >>= 1)
        s += __shfl_xor_sync(0xffffffffu, s, off);
    const float mu = s * (1.0f / 64.0f);

    const float dx = v.x - mu, dy = v.y - mu, dz = v.z - mu, dw = v.w - mu;
    float q = dx * dx + dy * dy + dz * dz + dw * dw;
    #pragma unroll
    for (int off = 8; off; off >>= 1)
        q += __shfl_xor_sync(0xffffffffu, q, off);
    const float rs = rsqrtf(q * (1.0f / 64.0f) + LN_EPS);

    const float4 gg = __ldg((const float4*)g + li);
    const float4 bb = __ldg((const float4*)bln + li);
    float4 o;
    o.x = fmaf(dx * rs, gg.x, bb.x);
    o.y = fmaf(dy * rs, gg.y, bb.y);
    o.z = fmaf(dz * rs, gg.z, bb.z);
    o.w = fmaf(dw * rs, gg.w, bb.w);
    o.x *= fsig(o.x);
    o.y *= fsig(o.y);
    o.z *= fsig(o.z);
    o.w *= fsig(o.w);
    ((float4*)io)[(size_t)row * 16 + li] = o;
}

// ---------------------------------------------------------------------------
// Launch: pack -> compose -> prep -> edge -> layernorm.
// ---------------------------------------------------------------------------
extern "C" void kernel_launch(void* const* d_in, const int* in_sizes, int n_in,
                              void* d_out, int out_size)
{
    const float* h     = (const float*)d_in[0];
    const float* dist  = (const float*)d_in[1];
    const int*   edges = (const int*)d_in[2];   // JAX x64-disabled => int32
    /* d_in[3] node_mask: unused by the reference */
    const float* emask = (const float*)d_in[4];
    const float* Wlin  = (const float*)d_in[5];
    const float* blin  = (const float*)d_in[6];
    const float* W1    = (const float*)d_in[7];
    const float* b1    = (const float*)d_in[8];
    const float* W2    = (const float*)d_in[9];
    const float* b2    = (const float*)d_in[10];
    const float* lng   = (const float*)d_in[11];
    const float* lnb   = (const float*)d_in[12];
    float* out = (float*)d_out;

    cudaFuncSetAttribute(prep_kernel,
                         cudaFuncAttributeMaxDynamicSharedMemorySize, PREP_SMEM);

    pack_kernel<<<(E_EDGES + 511) / 512, 512>>>(edges, dist, emask);
    compose_kernel<<<16, 256>>>(Wlin, blin, W1);
    prep_kernel<<<592, 256, PREP_SMEM>>>(h, out);
    edge_kernel<<<1184, 256>>>(W1, b1, W2, b2, out);
    ln_kernel<<<(N_NODES + 15) / 16, 256>>>(lng, lnb, out);
}

// round 8
// speedup vs baseline: 1.4860x; 1.1389x over previous
#include <cuda_runtime.h>
#include <cuda_bf16.h>
#include <cstdint>
#include <cstddef>

#define N_NODES 100000
#define E_EDGES 1000000
#define D_DIM   64
#define NORM_INV 0.01f
#define LN_EPS  1e-5f

// Composite stacked weights: rows 0-63 Wlin, 64-127 Wu=A@Wlin, 128-191 Wv=B@Wlin
__device__ float g_Ws[192 * 64];
__device__ float g_bs[192];           // {blin, A@blin, B@blin}
// Per-node features for the edge kernel (bf16; att path is /100-damped)
__device__ __nv_bfloat16 g_uv[(size_t)N_NODES * 128];  // [node][0:64]=u, [64:128]=v
__device__ __nv_bfloat16 g_xc[(size_t)N_NODES * 64];   // x copy for scatter values
// Packed per-edge metadata {row, col, dist, emask} (16 B)
__device__ int4 g_ep[(size_t)E_EDGES];

// Exact sigmoid (used output-side in LN)
__device__ __forceinline__ float fsig(float v) {
    return __fdividef(1.0f, 1.0f + __expf(-v));
}
// Fast sigmoid via HW tanh (att path; /100-damped)
__device__ __forceinline__ float fsig_t(float v) {
    float t;
    asm("tanh.approx.f32 %0, %1;" : "=f"(t) : "f"(v * 0.5f));
    return fmaf(t, 0.5f, 0.5f);
}

__device__ __forceinline__ void red_add_v4(float* dst, float a, float b,
                                           float c, float d) {
    asm volatile("red.global.add.v4.f32 [%0], {%1, %2, %3, %4};"
                 :: "l"(dst), "f"(a), "f"(b), "f"(c), "f"(d) : "memory");
}

__device__ __forceinline__ float4 bf16x4_to_f4(uint2 r) {
    const float2 a = __bfloat1622float2(*reinterpret_cast<__nv_bfloat162*>(&r.x));
    const float2 b = __bfloat1622float2(*reinterpret_cast<__nv_bfloat162*>(&r.y));
    return make_float4(a.x, a.y, b.x, b.y);
}

// ---------------------------------------------------------------------------
// Kernel P (pack): g_ep[e] = {row, col, dist, emask}.
// ---------------------------------------------------------------------------
__global__ void pack_kernel(const int* __restrict__ edges,
                            const float* __restrict__ dist,
                            const float* __restrict__ emask)
{
    const int e = blockIdx.x * blockDim.x + threadIdx.x;
    if (e >= E_EDGES) return;
    int4 m;
    m.x = edges[e];
    m.y = edges[E_EDGES + e];
    m.z = __float_as_int(dist[e]);
    m.w = __float_as_int(emask[e]);
    g_ep[e] = m;
}

// ---------------------------------------------------------------------------
// Kernel 0 (compose): Wu = A@Wlin, Wv = B@Wlin, bu = A@blin, bv = B@blin.
// ---------------------------------------------------------------------------
__global__ void compose_kernel(const float* __restrict__ Wlin,
                               const float* __restrict__ blin,
                               const float* __restrict__ W1)
{
    __shared__ float sWlin[4096], sA[4096], sB[4096];
    const int tid = threadIdx.x;
    for (int i = tid; i < 4096; i += 256) {
        sWlin[i] = Wlin[i];
        const int r = i >> 6, c = i & 63;
        sA[i] = W1[r * 129 + c];
        sB[i] = W1[r * 129 + 64 + c];
    }
    __syncthreads();

    if (blockIdx.x == 0) {
        for (int i = tid; i < 4096; i += 256) g_Ws[i] = sWlin[i];
        if (tid < 64) {
            g_bs[tid] = blin[tid];
            float su = 0.f, sv = 0.f;
            for (int m = 0; m < 64; m++) {
                const float bm = __ldg(blin + m);
                su = fmaf(sA[tid * 64 + m], bm, su);
                sv = fmaf(sB[tid * 64 + m], bm, sv);
            }
            g_bs[64 + tid]  = su;
            g_bs[128 + tid] = sv;
        }
    }

    for (int idx = blockIdx.x * 256 + tid; idx < 4096; idx += gridDim.x * 256) {
        const int j = idx >> 6, k = idx & 63;
        float su = 0.f, sv = 0.f;
        #pragma unroll 8
        for (int m = 0; m < 64; m++) {
            const float w = sWlin[m * 64 + k];
            su = fmaf(sA[j * 64 + m], w, su);
            sv = fmaf(sB[j * 64 + m], w, sv);
        }
        g_Ws[4096 + idx] = su;
        g_Ws[8192 + idx] = sv;
    }
}

// ---------------------------------------------------------------------------
// Kernel 1 (prep): one stacked GEMM per node: {x,u,v} = Ws @ h + bs.
// ---------------------------------------------------------------------------
#define PREP_SMEM ((192 * 68 + 192) * 4 + 8 * 8 * 64 * 4)   // 69,376 B

__global__ void __launch_bounds__(256, 2)
prep_kernel(const float* __restrict__ h,
            float* __restrict__ out_res)
{
    extern __shared__ float smem[];
    float*  sWs = smem;                    // 192*68
    float*  sbs = sWs + 192 * 68;          // 192
    float4* sH  = (float4*)(sbs + 192);    // [8 warps][8 nodes][16 f4]

    const int tid = threadIdx.x;
    for (int i = tid; i < 192 * 64; i += 256)
        sWs[(i >> 6) * 68 + (i & 63)] = g_Ws[i];
    if (tid < 192) sbs[tid] = g_bs[tid];
    __syncthreads();

    const int lane = tid & 31;
    const int w    = tid >> 5;
    const int warpGlobal = blockIdx.x * 8 + w;
    const int nWarps     = gridDim.x * 8;

    const float4* wp[6];
    float bj[6];
    #pragma unroll
    for (int g = 0; g < 6; g++) {
        wp[g] = ((const float4*)sWs) + (g * 32 + lane) * 17;
        bj[g] = sbs[g * 32 + lane];
    }
    const float4* hf4 = (const float4*)h;
    float4* sHw = sH + w * (8 * 16);

    for (int nb = warpGlobal * 8; nb < N_NODES; nb += nWarps * 8) {
        #pragma unroll
        for (int ep = 0; ep < 8; ep += 2) {
            const int e  = ep + (lane >> 4);
            const int li = lane & 15;
            sHw[e * 16 + li] = hf4[(size_t)(nb + e) * 16 + li];
        }
        __syncwarp();

        float acc[6][8];
        #pragma unroll
        for (int g = 0; g < 6; g++)
            #pragma unroll
            for (int e = 0; e < 8; e++) acc[g][e] = bj[g];

        #pragma unroll 2
        for (int kk = 0; kk < 16; kk++) {
            float4 wr[6];
            #pragma unroll
            for (int g = 0; g < 6; g++) wr[g] = wp[g][kk];
            #pragma unroll
            for (int e = 0; e < 8; e++) {
                const float4 xv = sHw[e * 16 + kk];   // warp-uniform broadcast
                #pragma unroll
                for (int g = 0; g < 6; g++) {
                    acc[g][e] = fmaf(wr[g].x, xv.x, acc[g][e]);
                    acc[g][e] = fmaf(wr[g].y, xv.y, acc[g][e]);
                    acc[g][e] = fmaf(wr[g].z, xv.z, acc[g][e]);
                    acc[g][e] = fmaf(wr[g].w, xv.w, acc[g][e]);
                }
            }
        }

        #pragma unroll
        for (int e = 0; e < 8; e++) {
            const size_t n64  = (size_t)(nb + e) * 64;
            const size_t n128 = (size_t)(nb + e) * 128;
            out_res[n64 + lane]      = acc[0][e];
            out_res[n64 + lane + 32] = acc[1][e];
            g_xc[n64 + lane]       = __float2bfloat16(acc[0][e]);
            g_xc[n64 + lane + 32]  = __float2bfloat16(acc[1][e]);
            g_uv[n128 + lane]      = __float2bfloat16(acc[2][e]);
            g_uv[n128 + lane + 32] = __float2bfloat16(acc[3][e]);
            g_uv[n128 + 64 + lane]      = __float2bfloat16(acc[4][e]);
            g_uv[n128 + 64 + lane + 32] = __float2bfloat16(acc[5][e]);
        }
        __syncwarp();
    }
}

// ---------------------------------------------------------------------------
// Kernel 2 (edge): t = u[row]+v[col]+wd*d+b1; att = sig(W2.silu(t)+b2);
// fp32 red.global.add.v4 of att*x_col into d_out[row].
// 4 edges per warp-iter; all gathers batched up front for MLP.
// ---------------------------------------------------------------------------
__global__ void edge_kernel(const float* __restrict__ W1,   // [64][129]
                            const float* __restrict__ b1,
                            const float* __restrict__ W2,   // [64]
                            const float* __restrict__ b2p,
                            float* __restrict__ agg)        // d_out
{
    const int lane = threadIdx.x & 31;
    const int w    = threadIdx.x >> 5;
    const int hw   = lane >> 4;      // which edge of the pair
    const int li   = lane & 15;      // dim group within edge

    const float4 w2_4 = ((const float4*)W2)[li];
    const float4 b1_4 = ((const float4*)b1)[li];
    float4 wd_4;
    wd_4.x = __ldg(W1 + (size_t)(li * 4 + 0) * 129 + 128);
    wd_4.y = __ldg(W1 + (size_t)(li * 4 + 1) * 129 + 128);
    wd_4.z = __ldg(W1 + (size_t)(li * 4 + 2) * 129 + 128);
    wd_4.w = __ldg(W1 + (size_t)(li * 4 + 3) * 129 + 128);
    const float b2 = b2p[0];

    const uint2* uvp = (const uint2*)g_uv;   // 32 uint2 per node (u:0-15, v:16-31)
    const uint2* xcp = (const uint2*)g_xc;   // 16 uint2 per node

    const int warpGlobal = blockIdx.x * 8 + w;
    const int nWarps     = gridDim.x * 8;

    for (int eb = warpGlobal * 4; eb < E_EDGES; eb += nWarps * 4) {
        // Batch metadata + gathers for both s-steps (independent chains)
        int4 m[2];
        m[0] = __ldg(g_ep + eb + hw);
        m[1] = __ldg(g_ep + eb + 2 + hw);

        uint2 ur[2], vr[2], xr[2];
        #pragma unroll
        for (int s = 0; s < 2; s++) {
            ur[s] = __ldg(uvp + (size_t)m[s].x * 32 + li);
            vr[s] = __ldg(uvp + (size_t)m[s].y * 32 + 16 + li);
            xr[s] = __ldg(xcp + (size_t)m[s].y * 16 + li);
        }

        #pragma unroll
        for (int s = 0; s < 2; s++) {
            const float d  = __int_as_float(m[s].z);
            const float em = __int_as_float(m[s].w);
            const float4 u4 = bf16x4_to_f4(ur[s]);
            const float4 v4 = bf16x4_to_f4(vr[s]);
            const float4 x4 = bf16x4_to_f4(xr[s]);

            float4 t;
            t.x = fmaf(d, wd_4.x, u4.x + v4.x + b1_4.x);
            t.y = fmaf(d, wd_4.y, u4.y + v4.y + b1_4.y);
            t.z = fmaf(d, wd_4.z, u4.z + v4.z + b1_4.z);
            t.w = fmaf(d, wd_4.w, u4.w + v4.w + b1_4.w);

            const float h0 = t.x * fsig_t(t.x);
            const float h1 = t.y * fsig_t(t.y);
            const float h2 = t.z * fsig_t(t.z);
            const float h3 = t.w * fsig_t(t.w);

            float p = fmaf(h0, w2_4.x,
                      fmaf(h1, w2_4.y,
                      fmaf(h2, w2_4.z, h3 * w2_4.w)));
            #pragma unroll
            for (int off = 8; off; off >>= 1)          // reduce within 16 lanes
                p += __shfl_xor_sync(0xffffffffu, p, off);

            const float att = fsig_t(p + b2) * em * NORM_INV;

            float* dst = agg + (size_t)m[s].x * 64 + li * 4;
            red_add_v4(dst, x4.x * att, x4.y * att, x4.z * att, x4.w * att);
        }
    }
}

// ---------------------------------------------------------------------------
// Kernel 3: out = silu(LN(io)).  io holds x + agg (fp32).
// 16 lanes per row (float4 per lane), 2 rows per warp. Exact sigmoid.
// ---------------------------------------------------------------------------
__global__ void ln_kernel(const float* __restrict__ g,
                          const float* __restrict__ bln,
                          float* __restrict__ io)
{
    const int lane = threadIdx.x & 31;
    const int w    = threadIdx.x >> 5;
    const int li   = lane & 15;
    const int row  = blockIdx.x * 16 + w * 2 + (lane >> 4);
    if (row >= N_NODES) return;

    float4 v = ((const float4*)io)[(size_t)row * 16 + li];

    float s = v.x + v.y + v.z + v.w;
    #pragma unroll
    for (int off = 8; off; off >>= 1)
        s += __shfl_xor_sync(0xffffffffu, s, off);
    const float mu = s * (1.0f / 64.0f);

    const float dx = v.x - mu, dy = v.y - mu, dz = v.z - mu, dw = v.w - mu;
    float q = dx * dx + dy * dy + dz * dz + dw * dw;
    #pragma unroll
    for (int off = 8; off; off >>= 1)
        q += __shfl_xor_sync(0xffffffffu, q, off);
    const float rs = rsqrtf(q * (1.0f / 64.0f) + LN_EPS);

    const float4 gg = __ldg((const float4*)g + li);
    const float4 bb = __ldg((const float4*)bln + li);
    float4 o;
    o.x = fmaf(dx * rs, gg.x, bb.x);
    o.y = fmaf(dy * rs, gg.y, bb.y);
    o.z = fmaf(dz * rs, gg.z, bb.z);
    o.w = fmaf(dw * rs, gg.w, bb.w);
    o.x *= fsig(o.x);
    o.y *= fsig(o.y);
    o.z *= fsig(o.z);
    o.w *= fsig(o.w);
    ((float4*)io)[(size_t)row * 16 + li] = o;
}

// ---------------------------------------------------------------------------
// Launch: pack -> compose -> prep -> edge -> layernorm.
// ---------------------------------------------------------------------------
extern "C" void kernel_launch(void* const* d_in, const int* in_sizes, int n_in,
                              void* d_out, int out_size)
{
    const float* h     = (const float*)d_in[0];
    const float* dist  = (const float*)d_in[1];
    const int*   edges = (const int*)d_in[2];   // JAX x64-disabled => int32
    /* d_in[3] node_mask: unused by the reference */
    const float* emask = (const float*)d_in[4];
    const float* Wlin  = (const float*)d_in[5];
    const float* blin  = (const float*)d_in[6];
    const float* W1    = (const float*)d_in[7];
    const float* b1    = (const float*)d_in[8];
    const float* W2    = (const float*)d_in[9];
    const float* b2    = (const float*)d_in[10];
    const float* lng   = (const float*)d_in[11];
    const float* lnb   = (const float*)d_in[12];
    float* out = (float*)d_out;

    cudaFuncSetAttribute(prep_kernel,
                         cudaFuncAttributeMaxDynamicSharedMemorySize, PREP_SMEM);

    pack_kernel<<<(E_EDGES + 511) / 512, 512>>>(edges, dist, emask);
    compose_kernel<<<16, 256>>>(Wlin, blin, W1);
    prep_kernel<<<592, 256, PREP_SMEM>>>(h, out);
    edge_kernel<<<740, 256>>>(W1, b1, W2, b2, out);      // 5 blocks/SM, 1 wave
    ln_kernel<<<(N_NODES + 15) / 16, 256>>>(lng, lnb, out);
}